// round 16
// baseline (speedup 1.0000x reference)
#include <cuda_runtime.h>
#include <cstdint>

#define GRIDW 480
#define NPTS 100000
#define PTOT 400000
#define NCELL (4*GRIDW*GRIDW)      // 921600
#define NSM 148
#define NTHR 512
#define NWARPS (NSM*16)            // 2368
#define NGROUP (PTOT/16)           // 25000 warp-tiles of 16 points

// ---------------- smem layout (u32 offsets) ----------------
#define SW2 0        // W2 B-frags fp16: 4nc x 8ks x 8nt x 64 = 16384 u32
#define SW3 16384    // W3 B-frags fp16: 4nc x 4kt x 8nt x 64 = 8192 u32
#define SW1F 24576   // W1 B-frags fp16 (m16n8k8): 16nt x 32lane = 512 u32
#define SB1H 25088   // packed fp16x2 b1 pairs: nt*4+tig -> 64 u32
#define SB2 25152    // 256 f32
#define SB3 25408    // 64 f32
#define SMEM_U32 25472
#define SMEM_BYTES (SMEM_U32*4)    // 101888 B

// ---------------- device scratch ----------------
__device__ int g_cnt[NCELL];      // zero at load; self-resetting (scan clears)
__device__ int g_rank[NCELL];     // (rank<<1)|solo for occupied cells
__device__ int g_bsum[1024];      // lookback state; reset by k_mark each call

#define AGGF (1u << 30)
#define PREF (1u << 31)
#define VALM 0xFFFFFFu

// ---------------- helpers ----------------
__device__ __forceinline__ uint32_t f2h2(float lo, float hi) {
    uint32_t r;
    asm("cvt.rn.f16x2.f32 %0, %1, %2;" : "=r"(r) : "f"(hi), "f"(lo));
    return r;
}
__device__ __forceinline__ unsigned short f2h(float f) {
    unsigned short h;
    asm("cvt.rn.f16.f32 %0, %1;" : "=h"(h) : "f"(f));
    return h;
}
__device__ __forceinline__ uint32_t hrelu2(uint32_t a) {
    uint32_t r;
    asm("max.f16x2 %0, %1, %2;" : "=r"(r) : "r"(a), "r"(0u));
    return r;
}
__device__ __forceinline__ void mma16(float* d, const uint32_t* a, uint32_t b0, uint32_t b1) {
    asm volatile("mma.sync.aligned.m16n8k16.row.col.f32.f16.f16.f32 "
        "{%0,%1,%2,%3},{%4,%5,%6,%7},{%8,%9},{%0,%1,%2,%3};"
        : "+f"(d[0]), "+f"(d[1]), "+f"(d[2]), "+f"(d[3])
        : "r"(a[0]), "r"(a[1]), "r"(a[2]), "r"(a[3]), "r"(b0), "r"(b1));
}
// fp16-accumulate m16n8k8: D/C are 2 packed fp16x2 regs (== L2 A-frag halves)
__device__ __forceinline__ void mma8h(uint32_t* d, uint32_t a0, uint32_t a1, uint32_t b0) {
    asm volatile("mma.sync.aligned.m16n8k8.row.col.f16.f16.f16.f16 "
        "{%0,%1},{%2,%3},{%4},{%0,%1};"
        : "+r"(d[0]), "+r"(d[1])
        : "r"(a0), "r"(a1), "r"(b0));
}
__device__ __forceinline__ void atomic_fmax(float* addr, float v) {
    if (v >= 0.0f) atomicMax((int*)addr, __float_as_int(v));
    else atomicMin((unsigned int*)addr, __float_as_uint(v));
}

// ---------------- small kernels ----------------
__global__ void k_mark(const int* __restrict__ xy) {
    int p = blockIdx.x * blockDim.x + threadIdx.x;
    if (p < 1024) g_bsum[p] = 0;          // reset lookback state for k_scan
    if (p < PTOT) {
        int2 v = ((const int2*)xy)[p];
        int b = p / NPTS;
        atomicAdd(&g_cnt[(b * GRIDW + v.x) * GRIDW + v.y], 1);
    }
}

// single-pass scan with decoupled lookback: counts -> ranks + unq + pooled -inf init
__global__ void k_scan(float* unq_out, uint2* pooled) {
    __shared__ int ws[32];
    __shared__ int s_off;
    int t = threadIdx.x;
    int lane = t & 31, wid = t >> 5;
    int i = blockIdx.x * 1024 + t;

    int c = g_cnt[i];
    if (c) g_cnt[i] = 0;                  // self-reset for next replay
    int v = (c != 0);
    unsigned int m = __ballot_sync(0xffffffffu, v);
    int excl = __popc(m & ((1u << lane) - 1u));
    if (lane == 31) ws[wid] = excl + v;
    __syncthreads();
    if (wid == 0) {
        int x = ws[lane];
        #pragma unroll
        for (int d = 1; d < 32; d <<= 1) {
            int o = __shfl_up_sync(0xffffffffu, x, d);
            if (lane >= d) x += o;
        }
        ws[lane] = x;
    }
    __syncthreads();
    int partial = excl + (wid ? ws[wid - 1] : 0);
    int tot = ws[31];

    // decoupled lookback (blocks dispatch in order; predecessors make progress)
    if (t == 0) {
        if (blockIdx.x == 0) {
            atomicExch(&g_bsum[0], (int)((unsigned)tot | PREF));
            s_off = 0;
        } else {
            atomicExch(&g_bsum[blockIdx.x], (int)((unsigned)tot | AGGF));
            int off = 0;
            int j = blockIdx.x - 1;
            while (1) {
                unsigned e = (unsigned)atomicAdd(&g_bsum[j], 0);
                if (e & PREF) { off += (int)(e & VALM); break; }
                if (e & AGGF) { off += (int)(e & VALM); j--; }
            }
            atomicExch(&g_bsum[blockIdx.x], (int)((unsigned)(off + tot) | PREF));
            s_off = off;
        }
    }
    __syncthreads();
    int r = partial + s_off;

    int solo = (c == 1);
    if (v) {
        g_rank[i] = (r << 1) | solo;
        if (unq_out) {
            int b = i / (GRIDW * GRIDW);
            int rem = i - b * GRIDW * GRIDW;
            unq_out[3 * r + 0] = (float)b;
            unq_out[3 * r + 1] = (float)(rem / GRIDW);
            unq_out[3 * r + 2] = (float)(rem % GRIDW);
        }
    }
    // warp-cooperative -inf init of non-solo rows (coalesced 256B per row)
    unsigned int nm = __ballot_sync(0xffffffffu, v && !solo);
    uint2 ninf = make_uint2(0xff800000u, 0xff800000u);
    while (nm) {
        int src = __ffs(nm) - 1;
        nm &= nm - 1;
        int rr = __shfl_sync(0xffffffffu, r, src);
        pooled[(size_t)rr * 32 + lane] = ninf;
    }
}

// ---------------- fused all-tensor MLP: L1 fp16-acc m16n8k8, L2/L3 m16n8k16 -------
__global__ void __launch_bounds__(NTHR, 1)
k_mlp(const float* __restrict__ pt_fea, const int* __restrict__ xy,
      const float* __restrict__ W1g, const float* __restrict__ b1g,
      const float* __restrict__ W2g, const float* __restrict__ b2g,
      const float* __restrict__ W3g, const float* __restrict__ b3g,
      float* __restrict__ pooled) {
    extern __shared__ uint32_t sm[];
    float* smf = (float*)sm;
    int t = threadIdx.x;

    // ---- stage W2 as fp16 B-frags: sm[SW2 + ((nc*8+ks)*8+nt)*64 + lane*2 + j] ----
    for (int idx = t; idx < 16384; idx += NTHR) {
        int j = idx & 1, lane = (idx >> 1) & 31, nt = (idx >> 6) & 7,
            ks = (idx >> 9) & 7, nc = idx >> 12;
        int k = ks * 16 + (lane & 3) * 2 + j * 8;
        int n = nc * 64 + nt * 8 + (lane >> 2);
        sm[SW2 + idx] = (uint32_t)f2h(W2g[k * 256 + n]) |
                        ((uint32_t)f2h(W2g[(k + 1) * 256 + n]) << 16);
    }
    // ---- stage W3 as fp16 B-frags: sm[SW3 + ((nc*4+kt)*8+nt)*64 + lane*2 + j] ----
    for (int idx = t; idx < 8192; idx += NTHR) {
        int j = idx & 1, lane = (idx >> 1) & 31, nt = (idx >> 6) & 7,
            kt = (idx >> 9) & 3, nc = idx >> 11;
        int k = nc * 64 + kt * 16 + (lane & 3) * 2 + j * 8;
        int n = nt * 8 + (lane >> 2);
        sm[SW3 + idx] = (uint32_t)f2h(W3g[k * 64 + n]) |
                        ((uint32_t)f2h(W3g[(k + 1) * 64 + n]) << 16);
    }
    // ---- stage W1 as m16n8k8 B-frags: sm[SW1F + nt*32 + lane], K padded 3->8 ----
    if (t < 512) {
        int lane = t & 31, nt = t >> 5;
        int k = (lane & 3) * 2;
        int n = nt * 8 + (lane >> 2);
        unsigned short lo = (k < 3)     ? f2h(W1g[k * 128 + n])       : (unsigned short)0;
        unsigned short hi = (k + 1 < 3) ? f2h(W1g[(k + 1) * 128 + n]) : (unsigned short)0;
        sm[SW1F + t] = (uint32_t)lo | ((uint32_t)hi << 16);
    }
    // packed fp16x2 b1 pairs: nt*4+tig -> (b1[nt*8+2tig], b1[nt*8+2tig+1])
    if (t < 64) {
        int tig = t & 3, nt = t >> 2;
        int col = nt * 8 + 2 * tig;
        sm[SB1H + t] = (uint32_t)f2h(b1g[col]) | ((uint32_t)f2h(b1g[col + 1]) << 16);
    }
    if (t < 64) { smf[SB2 + t] = b2g[t]; smf[SB2 + 64 + t] = b2g[64 + t];
                  smf[SB2 + 128 + t] = b2g[128 + t]; smf[SB2 + 192 + t] = b2g[192 + t];
                  smf[SB3 + t] = b3g[t]; }
    __syncthreads();

    const int lane = t & 31;
    const int gq = lane >> 2, tig = lane & 3;
    const int warp = blockIdx.x * (NTHR / 32) + (t >> 5);
    const int2* __restrict__ xy2 = (const int2*)xy;

    // ---- prologue: resolve first tile's rank chain up front ----
    int grp = warp;
    int r0 = 0, r1 = 0;
    {
        int p0 = grp * 16 + gq, p1 = p0 + 8;
        int2 v0 = xy2[p0], v1 = xy2[p1];
        r0 = g_rank[((p0 / NPTS) * GRIDW + v0.x) * GRIDW + v0.y];
        r1 = g_rank[((p1 / NPTS) * GRIDW + v1.x) * GRIDW + v1.y];
    }

    #pragma unroll 1
    while (grp < NGROUP) {
        int p0 = grp * 16 + gq, p1 = p0 + 8;
        float x00 = pt_fea[p0 * 3], x01 = pt_fea[p0 * 3 + 1], x02 = pt_fea[p0 * 3 + 2];
        float x10 = pt_fea[p1 * 3], x11 = pt_fea[p1 * 3 + 1], x12 = pt_fea[p1 * 3 + 2];

        // prefetch next tile's xy (first link of the rank chain)
        int ngrp = grp + NWARPS;
        bool more = ngrp < NGROUP;
        int2 nv0, nv1;
        if (more) {
            int q0 = ngrp * 16 + gq;
            nv0 = xy2[q0]; nv1 = xy2[q0 + 8];
        }

        // ---- X as m16n8k8 fp16 A-fragment (K padded 3->8; only tig<2 non-zero) ----
        uint32_t xa0, xa1;
        if (tig == 0)      { xa0 = f2h2(x00, x01); xa1 = f2h2(x10, x11); }
        else if (tig == 1) { xa0 = f2h2(x02, 0.f); xa1 = f2h2(x12, 0.f); }
        else               { xa0 = 0u; xa1 = 0u; }

        // ---- layer 1: fp16-acc mma8, bias-seeded; D regs ARE the L2 A-frag halves
        uint32_t A[8][4];
        #pragma unroll
        for (int ks = 0; ks < 8; ks++) {
            int ntE = 2 * ks, ntO = ntE + 1;
            uint32_t bE = sm[SB1H + ntE * 4 + tig];
            uint32_t bO = sm[SB1H + ntO * 4 + tig];
            uint32_t dE[2] = {bE, bE};
            uint32_t dO[2] = {bO, bO};
            mma8h(dE, xa0, xa1, sm[SW1F + ntE * 32 + lane]);
            mma8h(dO, xa0, xa1, sm[SW1F + ntO * 32 + lane]);
            A[ks][0] = hrelu2(dE[0]);
            A[ks][1] = hrelu2(dE[1]);
            A[ks][2] = hrelu2(dO[0]);
            A[ks][3] = hrelu2(dO[1]);
        }

        // prefetch next tile's ranks (second link; xy arrived during layer 1)
        int nr0 = 0, nr1 = 0;
        if (more) {
            int q0 = ngrp * 16 + gq, q1 = q0 + 8;
            nr0 = g_rank[((q0 / NPTS) * GRIDW + nv0.x) * GRIDW + nv0.y];
            nr1 = g_rank[((q1 / NPTS) * GRIDW + nv1.x) * GRIDW + nv1.y];
        }

        float acc3[8][4];
        #pragma unroll
        for (int n = 0; n < 8; n++)
            #pragma unroll
            for (int q = 0; q < 4; q++) acc3[n][q] = 0.f;

        #pragma unroll 1
        for (int nc = 0; nc < 4; nc++) {
            const uint32_t* w2p = sm + SW2 + nc * 4096 + lane * 2;
            const uint32_t* w3p = sm + SW3 + nc * 2048 + lane * 2;
            #pragma unroll
            for (int kt = 0; kt < 4; kt++) {
                int ntA = 2 * kt, ntB = 2 * kt + 1;
                // bias-seeded L2 accumulators (no post-add needed)
                float2 bA = *(const float2*)(smf + SB2 + nc * 64 + ntA * 8 + 2 * tig);
                float2 bB = *(const float2*)(smf + SB2 + nc * 64 + ntB * 8 + 2 * tig);
                float accA[4] = {bA.x, bA.y, bA.x, bA.y};
                float accB[4] = {bB.x, bB.y, bB.x, bB.y};
                #pragma unroll
                for (int ks = 0; ks < 8; ks++) {
                    uint2 b2f = *(const uint2*)(w2p + (ks * 8 + ntA) * 64);
                    mma16(accA, A[ks], b2f.x, b2f.y);
                    uint2 b2s = *(const uint2*)(w2p + (ks * 8 + ntB) * 64);
                    mma16(accB, A[ks], b2s.x, b2s.y);
                }
                // convert: pack + relu only (bias already inside)
                uint32_t af[4];
                af[0] = hrelu2(f2h2(accA[0], accA[1]));
                af[1] = hrelu2(f2h2(accA[2], accA[3]));
                af[2] = hrelu2(f2h2(accB[0], accB[1]));
                af[3] = hrelu2(f2h2(accB[2], accB[3]));
                #pragma unroll
                for (int nt3 = 0; nt3 < 8; nt3++) {
                    uint2 b = *(const uint2*)(w3p + (kt * 8 + nt3) * 64);
                    mma16(acc3[nt3], af, b.x, b.y);
                }
            }
        }

        // ---- epilogue: +b3; solo fast STG, else sign-split atomics ----
        #pragma unroll
        for (int half = 0; half < 2; half++) {
            int r = half ? r1 : r0;
            size_t rb = (size_t)(r >> 1) * 64;
            if (r & 1) {
                float* dst = pooled + rb;
                #pragma unroll
                for (int nt3 = 0; nt3 < 8; nt3++) {
                    int col = nt3 * 8 + 2 * tig;
                    float2 val;
                    val.x = acc3[nt3][2 * half]     + smf[SB3 + col];
                    val.y = acc3[nt3][2 * half + 1] + smf[SB3 + col + 1];
                    *(float2*)(dst + col) = val;
                }
            } else {
                float* dst = pooled + rb;
                #pragma unroll
                for (int nt3 = 0; nt3 < 8; nt3++) {
                    int col = nt3 * 8 + 2 * tig;
                    atomic_fmax(dst + col,     acc3[nt3][2 * half]     + smf[SB3 + col]);
                    atomic_fmax(dst + col + 1, acc3[nt3][2 * half + 1] + smf[SB3 + col + 1]);
                }
            }
        }

        grp = ngrp;
        r0 = nr0; r1 = nr1;
    }
}

// ---------------- host launcher ----------------
extern "C" void kernel_launch(void* const* d_in, const int* in_sizes, int n_in,
                              void* d_out, int out_size) {
    const float* pt_fea = (const float*)d_in[0];
    const int*   xy     = (const int*)d_in[1];
    const float* W1     = (const float*)d_in[2];
    const float* b1     = (const float*)d_in[3];
    const float* W2     = (const float*)d_in[4];
    const float* b2     = (const float*)d_in[5];
    const float* W3     = (const float*)d_in[6];
    const float* b3     = (const float*)d_in[7];

    int M;
    float* unq_out;
    float* pooled;
    if (out_size % 67 == 0) {
        M = out_size / 67;
        unq_out = (float*)d_out;
        pooled = (float*)d_out + (size_t)3 * M;
    } else {
        M = out_size / 64;
        unq_out = nullptr;
        pooled = (float*)d_out;
    }

    cudaFuncSetAttribute(k_mlp, cudaFuncAttributeMaxDynamicSharedMemorySize, SMEM_BYTES);

    k_mark<<<(PTOT + 255) / 256, 256>>>(xy);
    k_scan<<<NCELL / 1024, 1024>>>(unq_out, (uint2*)pooled);
    k_mlp<<<NSM, NTHR, SMEM_BYTES>>>(pt_fea, xy, W1, b1, W2, b2, W3, b3, pooled);
}

// round 17
// speedup vs baseline: 1.0887x; 1.0887x over previous
#include <cuda_runtime.h>
#include <cstdint>

#define GRIDW 480
#define NPTS 100000
#define PTOT 400000
#define NCELL (4*GRIDW*GRIDW)      // 921600
#define NSM 148
#define NTHR 512
#define NWARPS (NSM*16)            // 2368
#define NGROUP (PTOT/16)           // 25000 warp-tiles of 16 points

// ---------------- smem layout (u32 offsets) ----------------
#define SW2 0        // W2 B-frags fp16: 4nc x 8ks x 8nt x 64 = 16384 u32
#define SW3 16384    // W3 B-frags fp16: 4nc x 4kt x 8nt x 64 = 8192 u32
#define SW1F 24576   // W1 B-frags fp16 (m16n8k8): 16nt x 32lane = 512 u32
#define SB1H 25088   // packed fp16x2 b1 pairs: nt*4+tig -> 64 u32
#define SB2 25152    // 256 f32
#define SB3 25408    // 64 f32
#define SMEM_U32 25472
#define SMEM_BYTES (SMEM_U32*4)    // 101888 B

// ---------------- device scratch ----------------
__device__ int g_cnt[NCELL];      // zero at load; self-resetting (scan1 clears)
__device__ int g_rank[NCELL];     // scan1: partial|flags ; scan3: (rank<<1)|solo
__device__ int g_bsum[1024];

// ---------------- helpers ----------------
__device__ __forceinline__ uint32_t f2h2(float lo, float hi) {
    uint32_t r;
    asm("cvt.rn.f16x2.f32 %0, %1, %2;" : "=r"(r) : "f"(hi), "f"(lo));
    return r;
}
__device__ __forceinline__ unsigned short f2h(float f) {
    unsigned short h;
    asm("cvt.rn.f16.f32 %0, %1;" : "=h"(h) : "f"(f));
    return h;
}
__device__ __forceinline__ uint32_t hrelu2(uint32_t a) {
    uint32_t r;
    asm("max.f16x2 %0, %1, %2;" : "=r"(r) : "r"(a), "r"(0u));
    return r;
}
__device__ __forceinline__ void mma16(float* d, const uint32_t* a, uint32_t b0, uint32_t b1) {
    asm volatile("mma.sync.aligned.m16n8k16.row.col.f32.f16.f16.f32 "
        "{%0,%1,%2,%3},{%4,%5,%6,%7},{%8,%9},{%0,%1,%2,%3};"
        : "+f"(d[0]), "+f"(d[1]), "+f"(d[2]), "+f"(d[3])
        : "r"(a[0]), "r"(a[1]), "r"(a[2]), "r"(a[3]), "r"(b0), "r"(b1));
}
// fp16-accumulate m16n8k8: D/C are 2 packed fp16x2 regs (== L2 A-frag halves)
__device__ __forceinline__ void mma8h(uint32_t* d, uint32_t a0, uint32_t a1, uint32_t b0) {
    asm volatile("mma.sync.aligned.m16n8k8.row.col.f16.f16.f16.f16 "
        "{%0,%1},{%2,%3},{%4},{%0,%1};"
        : "+r"(d[0]), "+r"(d[1])
        : "r"(a0), "r"(a1), "r"(b0));
}
__device__ __forceinline__ void atomic_fmax(float* addr, float v) {
    if (v >= 0.0f) atomicMax((int*)addr, __float_as_int(v));
    else atomicMin((unsigned int*)addr, __float_as_uint(v));
}

// ---------------- small kernels ----------------
__global__ void k_mark(const int* __restrict__ xy) {
    int p = blockIdx.x * blockDim.x + threadIdx.x;
    if (p < PTOT) {
        int2 v = ((const int2*)xy)[p];
        int b = p / NPTS;
        atomicAdd(&g_cnt[(b * GRIDW + v.x) * GRIDW + v.y], 1);
    }
}

// per-block exclusive scan of occupancy; packs occ/solo flags; zeroes g_cnt for next replay
__global__ void k_scan1() {
    __shared__ int ws[32];
    int i = blockIdx.x * 1024 + threadIdx.x;
    int lane = threadIdx.x & 31, wid = threadIdx.x >> 5;
    int c = g_cnt[i];
    if (c) g_cnt[i] = 0;                    // self-reset (write only if dirty)
    int v = (c != 0);
    unsigned int m = __ballot_sync(0xffffffffu, v);
    int excl = __popc(m & ((1u << lane) - 1u));
    if (lane == 31) ws[wid] = excl + v;
    __syncthreads();
    if (wid == 0) {
        int x = ws[lane];
        #pragma unroll
        for (int d = 1; d < 32; d <<= 1) {
            int o = __shfl_up_sync(0xffffffffu, x, d);
            if (lane >= d) x += o;
        }
        ws[lane] = x;
    }
    __syncthreads();
    int partial = excl + (wid ? ws[wid - 1] : 0);
    g_rank[i] = partial | (v << 16) | ((c == 1) << 17);
    if (threadIdx.x == 1023) g_bsum[blockIdx.x] = ws[31];
}

// finalize ranks (block offset computed inline from g_bsum), write unq rows,
// and -inf-init pooled rows of non-solo voxels (warp-cooperative, coalesced).
__global__ void k_scan3(float* unq_out, uint2* pooled) {
    __shared__ int ws[32];
    __shared__ int s_off;
    int t = threadIdx.x;
    int lane = t & 31, wid = t >> 5;

    int v = (t < blockIdx.x && t < 900) ? g_bsum[t] : 0;
    #pragma unroll
    for (int d = 16; d > 0; d >>= 1)
        v += __shfl_xor_sync(0xffffffffu, v, d);
    if (lane == 0) ws[wid] = v;
    __syncthreads();
    if (wid == 0) {
        int x = ws[lane];
        #pragma unroll
        for (int d = 16; d > 0; d >>= 1)
            x += __shfl_xor_sync(0xffffffffu, x, d);
        if (lane == 0) s_off = x;
    }
    __syncthreads();
    int off = s_off;

    int i = blockIdx.x * 1024 + t;
    int packed = g_rank[i];
    int occ = (packed >> 16) & 1;
    int solo = (packed >> 17) & 1;
    int r = (packed & 0xFFFF) + off;
    if (occ) {
        g_rank[i] = (r << 1) | solo;
        if (unq_out) {
            int b = i / (GRIDW * GRIDW);
            int rem = i - b * GRIDW * GRIDW;
            unq_out[3 * r + 0] = (float)b;
            unq_out[3 * r + 1] = (float)(rem / GRIDW);
            unq_out[3 * r + 2] = (float)(rem % GRIDW);
        }
    }
    unsigned int nm = __ballot_sync(0xffffffffu, occ && !solo);
    uint2 ninf = make_uint2(0xff800000u, 0xff800000u);
    while (nm) {
        int src = __ffs(nm) - 1;
        nm &= nm - 1;
        int rr = __shfl_sync(0xffffffffu, r, src);
        pooled[(size_t)rr * 32 + lane] = ninf;
    }
}

// ---------------- fused all-tensor MLP: L1 fp16-acc m16n8k8, L2/L3 m16n8k16 -------
__global__ void __launch_bounds__(NTHR, 1)
k_mlp(const float* __restrict__ pt_fea, const int* __restrict__ xy,
      const float* __restrict__ W1g, const float* __restrict__ b1g,
      const float* __restrict__ W2g, const float* __restrict__ b2g,
      const float* __restrict__ W3g, const float* __restrict__ b3g,
      float* __restrict__ pooled) {
    extern __shared__ uint32_t sm[];
    float* smf = (float*)sm;
    int t = threadIdx.x;

    // ---- stage W2 as fp16 B-frags: sm[SW2 + ((nc*8+ks)*8+nt)*64 + lane*2 + j] ----
    for (int idx = t; idx < 16384; idx += NTHR) {
        int j = idx & 1, lane = (idx >> 1) & 31, nt = (idx >> 6) & 7,
            ks = (idx >> 9) & 7, nc = idx >> 12;
        int k = ks * 16 + (lane & 3) * 2 + j * 8;
        int n = nc * 64 + nt * 8 + (lane >> 2);
        sm[SW2 + idx] = (uint32_t)f2h(W2g[k * 256 + n]) |
                        ((uint32_t)f2h(W2g[(k + 1) * 256 + n]) << 16);
    }
    // ---- stage W3 as fp16 B-frags: sm[SW3 + ((nc*4+kt)*8+nt)*64 + lane*2 + j] ----
    for (int idx = t; idx < 8192; idx += NTHR) {
        int j = idx & 1, lane = (idx >> 1) & 31, nt = (idx >> 6) & 7,
            kt = (idx >> 9) & 3, nc = idx >> 11;
        int k = nc * 64 + kt * 16 + (lane & 3) * 2 + j * 8;
        int n = nt * 8 + (lane >> 2);
        sm[SW3 + idx] = (uint32_t)f2h(W3g[k * 64 + n]) |
                        ((uint32_t)f2h(W3g[(k + 1) * 64 + n]) << 16);
    }
    // ---- stage W1 as m16n8k8 B-frags: sm[SW1F + nt*32 + lane], K padded 3->8 ----
    if (t < 512) {
        int lane = t & 31, nt = t >> 5;
        int k = (lane & 3) * 2;
        int n = nt * 8 + (lane >> 2);
        unsigned short lo = (k < 3)     ? f2h(W1g[k * 128 + n])       : (unsigned short)0;
        unsigned short hi = (k + 1 < 3) ? f2h(W1g[(k + 1) * 128 + n]) : (unsigned short)0;
        sm[SW1F + t] = (uint32_t)lo | ((uint32_t)hi << 16);
    }
    // packed fp16x2 b1 pairs: nt*4+tig -> (b1[nt*8+2tig], b1[nt*8+2tig+1])
    if (t < 64) {
        int tig = t & 3, nt = t >> 2;
        int col = nt * 8 + 2 * tig;
        sm[SB1H + t] = (uint32_t)f2h(b1g[col]) | ((uint32_t)f2h(b1g[col + 1]) << 16);
    }
    if (t < 64) { smf[SB2 + t] = b2g[t]; smf[SB2 + 64 + t] = b2g[64 + t];
                  smf[SB2 + 128 + t] = b2g[128 + t]; smf[SB2 + 192 + t] = b2g[192 + t];
                  smf[SB3 + t] = b3g[t]; }
    __syncthreads();

    const int lane = t & 31;
    const int gq = lane >> 2, tig = lane & 3;
    const int warp = blockIdx.x * (NTHR / 32) + (t >> 5);
    const int2* __restrict__ xy2 = (const int2*)xy;

    // ---- prologue: resolve first tile's rank chain up front ----
    int grp = warp;
    int r0 = 0, r1 = 0;
    {
        int p0 = grp * 16 + gq, p1 = p0 + 8;
        int2 v0 = xy2[p0], v1 = xy2[p1];
        r0 = g_rank[((p0 / NPTS) * GRIDW + v0.x) * GRIDW + v0.y];
        r1 = g_rank[((p1 / NPTS) * GRIDW + v1.x) * GRIDW + v1.y];
    }

    #pragma unroll 1
    while (grp < NGROUP) {
        int p0 = grp * 16 + gq, p1 = p0 + 8;
        float x00 = pt_fea[p0 * 3], x01 = pt_fea[p0 * 3 + 1], x02 = pt_fea[p0 * 3 + 2];
        float x10 = pt_fea[p1 * 3], x11 = pt_fea[p1 * 3 + 1], x12 = pt_fea[p1 * 3 + 2];

        // prefetch next tile's xy (first link of the rank chain)
        int ngrp = grp + NWARPS;
        bool more = ngrp < NGROUP;
        int2 nv0, nv1;
        if (more) {
            int q0 = ngrp * 16 + gq;
            nv0 = xy2[q0]; nv1 = xy2[q0 + 8];
        }

        // ---- X as m16n8k8 fp16 A-fragment (K padded 3->8; only tig<2 non-zero) ----
        uint32_t xa0, xa1;
        if (tig == 0)      { xa0 = f2h2(x00, x01); xa1 = f2h2(x10, x11); }
        else if (tig == 1) { xa0 = f2h2(x02, 0.f); xa1 = f2h2(x12, 0.f); }
        else               { xa0 = 0u; xa1 = 0u; }

        // ---- layer 1: fp16-acc mma8, bias-seeded; D regs ARE the L2 A-frag halves
        uint32_t A[8][4];
        #pragma unroll
        for (int ks = 0; ks < 8; ks++) {
            int ntE = 2 * ks, ntO = ntE + 1;
            uint32_t bE = sm[SB1H + ntE * 4 + tig];
            uint32_t bO = sm[SB1H + ntO * 4 + tig];
            uint32_t dE[2] = {bE, bE};
            uint32_t dO[2] = {bO, bO};
            mma8h(dE, xa0, xa1, sm[SW1F + ntE * 32 + lane]);
            mma8h(dO, xa0, xa1, sm[SW1F + ntO * 32 + lane]);
            A[ks][0] = hrelu2(dE[0]);
            A[ks][1] = hrelu2(dE[1]);
            A[ks][2] = hrelu2(dO[0]);
            A[ks][3] = hrelu2(dO[1]);
        }

        // prefetch next tile's ranks (second link; xy arrived during layer 1)
        int nr0 = 0, nr1 = 0;
        if (more) {
            int q0 = ngrp * 16 + gq, q1 = q0 + 8;
            nr0 = g_rank[((q0 / NPTS) * GRIDW + nv0.x) * GRIDW + nv0.y];
            nr1 = g_rank[((q1 / NPTS) * GRIDW + nv1.x) * GRIDW + nv1.y];
        }

        float acc3[8][4];
        #pragma unroll
        for (int n = 0; n < 8; n++)
            #pragma unroll
            for (int q = 0; q < 4; q++) acc3[n][q] = 0.f;

        #pragma unroll 1
        for (int nc = 0; nc < 4; nc++) {
            const uint32_t* w2p = sm + SW2 + nc * 4096 + lane * 2;
            const uint32_t* w3p = sm + SW3 + nc * 2048 + lane * 2;
            #pragma unroll
            for (int kt = 0; kt < 4; kt++) {
                int ntA = 2 * kt, ntB = 2 * kt + 1;
                // bias-seeded L2 accumulators (no post-add needed)
                float2 bA = *(const float2*)(smf + SB2 + nc * 64 + ntA * 8 + 2 * tig);
                float2 bB = *(const float2*)(smf + SB2 + nc * 64 + ntB * 8 + 2 * tig);
                float accA[4] = {bA.x, bA.y, bA.x, bA.y};
                float accB[4] = {bB.x, bB.y, bB.x, bB.y};
                #pragma unroll
                for (int ks = 0; ks < 8; ks++) {
                    uint2 b2f = *(const uint2*)(w2p + (ks * 8 + ntA) * 64);
                    mma16(accA, A[ks], b2f.x, b2f.y);
                    uint2 b2s = *(const uint2*)(w2p + (ks * 8 + ntB) * 64);
                    mma16(accB, A[ks], b2s.x, b2s.y);
                }
                // convert: pack + relu only (bias already inside)
                uint32_t af[4];
                af[0] = hrelu2(f2h2(accA[0], accA[1]));
                af[1] = hrelu2(f2h2(accA[2], accA[3]));
                af[2] = hrelu2(f2h2(accB[0], accB[1]));
                af[3] = hrelu2(f2h2(accB[2], accB[3]));
                #pragma unroll
                for (int nt3 = 0; nt3 < 8; nt3++) {
                    uint2 b = *(const uint2*)(w3p + (kt * 8 + nt3) * 64);
                    mma16(acc3[nt3], af, b.x, b.y);
                }
            }
        }

        // ---- epilogue: +b3; solo fast STG, else sign-split atomics ----
        #pragma unroll
        for (int half = 0; half < 2; half++) {
            int r = half ? r1 : r0;
            size_t rb = (size_t)(r >> 1) * 64;
            if (r & 1) {
                float* dst = pooled + rb;
                #pragma unroll
                for (int nt3 = 0; nt3 < 8; nt3++) {
                    int col = nt3 * 8 + 2 * tig;
                    float2 val;
                    val.x = acc3[nt3][2 * half]     + smf[SB3 + col];
                    val.y = acc3[nt3][2 * half + 1] + smf[SB3 + col + 1];
                    *(float2*)(dst + col) = val;
                }
            } else {
                float* dst = pooled + rb;
                #pragma unroll
                for (int nt3 = 0; nt3 < 8; nt3++) {
                    int col = nt3 * 8 + 2 * tig;
                    atomic_fmax(dst + col,     acc3[nt3][2 * half]     + smf[SB3 + col]);
                    atomic_fmax(dst + col + 1, acc3[nt3][2 * half + 1] + smf[SB3 + col + 1]);
                }
            }
        }

        grp = ngrp;
        r0 = nr0; r1 = nr1;
    }
}

// ---------------- host launcher ----------------
extern "C" void kernel_launch(void* const* d_in, const int* in_sizes, int n_in,
                              void* d_out, int out_size) {
    const float* pt_fea = (const float*)d_in[0];
    const int*   xy     = (const int*)d_in[1];
    const float* W1     = (const float*)d_in[2];
    const float* b1     = (const float*)d_in[3];
    const float* W2     = (const float*)d_in[4];
    const float* b2     = (const float*)d_in[5];
    const float* W3     = (const float*)d_in[6];
    const float* b3     = (const float*)d_in[7];

    int M;
    float* unq_out;
    float* pooled;
    if (out_size % 67 == 0) {
        M = out_size / 67;
        unq_out = (float*)d_out;
        pooled = (float*)d_out + (size_t)3 * M;
    } else {
        M = out_size / 64;
        unq_out = nullptr;
        pooled = (float*)d_out;
    }

    cudaFuncSetAttribute(k_mlp, cudaFuncAttributeMaxDynamicSharedMemorySize, SMEM_BYTES);

    k_mark<<<(PTOT + 255) / 256, 256>>>(xy);
    k_scan1<<<NCELL / 1024, 1024>>>();
    k_scan3<<<NCELL / 1024, 1024>>>(unq_out, (uint2*)pooled);
    k_mlp<<<NSM, NTHR, SMEM_BYTES>>>(pt_fea, xy, W1, b1, W2, b2, W3, b3, pooled);
}